// round 1
// baseline (speedup 1.0000x reference)
#include <cuda_runtime.h>
#include <math.h>

// Accumulators / corrections live in device globals (no allocation allowed).
__device__ double g_acc[2];
__device__ double g_corr[2];

// ---------------------------------------------------------------------------
// Setup kernel: recompute KTK exactly like the reference (fp64 -> fp32 cast),
// then compute the coordinate-bias correction
//   corr = mean_w [ x(w)^T M32 x(w) ]   (x = affine coord part; exact-M part is 0)
// via alpha = 1'M1, betaC = 1'Mc, gammaC = c'Mc, betaA = 1'Ma, gammaA = a'Ma.
// Also zeroes the flow accumulator.
// ---------------------------------------------------------------------------
template <int KZ>
__global__ void setup_kernel(int W, int flowIdx) {
    constexpr int K2 = KZ * KZ;
    __shared__ double Inv[9];
    __shared__ double Ksh[K2 * K2];
    __shared__ float  M32[K2 * K2];
    __shared__ double accs[5];  // alpha, betaC, gammaC, betaA, gammaA

    int tid = threadIdx.x;
    if (tid == 0) {
        double st = 0.0, st2 = 0.0;
        for (int t = 0; t < KZ; t++) { st += t; st2 += (double)t * t; }
        double G00 = KZ * st2, G01 = st * st, G02 = KZ * st;
        double G11 = KZ * st2, G12 = KZ * st, G22 = (double)K2;
        // symmetric 3x3 inverse via adjugate
        double c00 = G11 * G22 - G12 * G12;
        double c01 = G12 * G02 - G01 * G22;
        double c02 = G01 * G12 - G11 * G02;
        double det = G00 * c00 + G01 * c01 + G02 * c02;
        double id = 1.0 / det;
        Inv[0] = c00 * id;
        Inv[1] = c01 * id;
        Inv[2] = c02 * id;
        Inv[3] = c01 * id;
        Inv[4] = (G00 * G22 - G02 * G02) * id;
        Inv[5] = (G02 * G01 - G00 * G12) * id;
        Inv[6] = c02 * id;
        Inv[7] = (G02 * G01 - G00 * G12) * id;
        Inv[8] = (G00 * G11 - G01 * G01) * id;
        for (int i = 0; i < 5; i++) accs[i] = 0.0;
    }
    __syncthreads();

    // K = A (A'A)^-1 A' - I
    for (int e = tid; e < K2 * K2; e += blockDim.x) {
        int q = e / K2, r = e % K2;
        double Aq[3] = { (double)(q / KZ), (double)(q % KZ), 1.0 };
        double Ar[3] = { (double)(r / KZ), (double)(r % KZ), 1.0 };
        double p = 0.0;
        #pragma unroll
        for (int i = 0; i < 3; i++)
            #pragma unroll
            for (int j = 0; j < 3; j++)
                p += Aq[i] * Inv[i * 3 + j] * Ar[j];
        Ksh[e] = p - (q == r ? 1.0 : 0.0);
    }
    __syncthreads();

    // M64 = K'K (fp64), cast to fp32 like the reference
    for (int e = tid; e < K2 * K2; e += blockDim.x) {
        int q = e / K2, r = e % K2;
        double m = 0.0;
        for (int s = 0; s < K2; s++) m += Ksh[s * K2 + q] * Ksh[s * K2 + r];
        M32[e] = (float)m;
    }
    __syncthreads();

    if (tid < K2) {
        int q = tid;
        double rowsum = 0.0, rowc = 0.0, rowa = 0.0;
        for (int r = 0; r < K2; r++) {
            double m = (double)M32[q * K2 + r];
            rowsum += m;
            rowc += m * (double)(r % KZ);
            rowa += m * (double)(r / KZ);
        }
        atomicAdd(&accs[0], rowsum);
        atomicAdd(&accs[1], rowc);
        atomicAdd(&accs[2], (double)(q % KZ) * rowc);
        atomicAdd(&accs[3], rowa);
        atomicAdd(&accs[4], (double)(q / KZ) * rowa);
    }
    __syncthreads();

    if (tid == 0) {
        double alpha = accs[0], betaC = accs[1], gammaC = accs[2];
        double betaA = accs[3], gammaA = accs[4];
        double outN = (double)(W - KZ + 1);
        double Sw  = outN * (outN - 1.0) * 0.5;
        double Sw2 = (outN - 1.0) * outN * (2.0 * outN - 1.0) / 6.0;
        double corrX = (alpha * Sw2 + 2.0 * betaC * Sw) / outN + gammaC;  // gx: x = w*1 + c
        double corrY = (alpha * Sw2 + 2.0 * betaA * Sw) / outN + gammaA;  // gy: x = h*1 + a
        g_corr[flowIdx] = corrX + corrY;
        g_acc[flowIdx] = 0.0;
    }
}

// ---------------------------------------------------------------------------
// Main SSE kernel: per output pixel, affine-fit residual via centered moments.
//   SSE = Q - S^2/n - (Sa^2 + Sc^2)/(KZ*V)
// ---------------------------------------------------------------------------
__inline__ __device__ double warp_reduce(double v) {
    #pragma unroll
    for (int o = 16; o > 0; o >>= 1) v += __shfl_down_sync(0xffffffffu, v, o);
    return v;
}

template <int KZ>
__global__ void sse_kernel(const float* __restrict__ flow, int W, int outN, int flowIdx) {
    constexpr int BX = 32, BY = 8;
    constexpr int SW = BX + KZ - 1, SH = BY + KZ - 1;
    __shared__ float tile[SH][SW];
    __shared__ double wsum[BX * BY / 32];

    int img = blockIdx.z;
    const float* src = flow + (size_t)img * W * W;
    int ox0 = blockIdx.x * BX, oy0 = blockIdx.y * BY;

    int t = threadIdx.y * BX + threadIdx.x;
    for (int i = t; i < SH * SW; i += BX * BY) {
        int r = i / SW, c = i % SW;
        int gr = oy0 + r, gc = ox0 + c;
        float v = 0.0f;
        if (gr < W && gc < W) v = src[gr * W + gc];
        tile[r][c] = v;
    }
    __syncthreads();

    double sse = 0.0;
    int ox = ox0 + threadIdx.x, oy = oy0 + threadIdx.y;
    if (ox < outN && oy < outN) {
        const float mu = (KZ - 1) * 0.5f;
        float vsum = 0.0f;
        #pragma unroll
        for (int tt = 0; tt < KZ; tt++) vsum += (tt - mu) * (tt - mu);
        const float inv_n  = 1.0f / (float)(KZ * KZ);
        const float inv_kv = 1.0f / ((float)KZ * vsum);

        float S = 0.0f, Sa = 0.0f, Sc = 0.0f, Q = 0.0f;
        #pragma unroll
        for (int a = 0; a < KZ; a++) {
            float rs = 0.0f, rc = 0.0f, rq = 0.0f;
            #pragma unroll
            for (int c = 0; c < KZ; c++) {
                float p = tile[threadIdx.y + a][threadIdx.x + c];
                rs += p;
                rc += ((float)c - mu) * p;
                rq += p * p;
            }
            S += rs;
            Q += rq;
            Sc += rc;
            Sa += ((float)a - mu) * rs;
        }
        sse = (double)(Q - S * S * inv_n - (Sa * Sa + Sc * Sc) * inv_kv);
    }

    // block reduction -> one atomicAdd per block
    double v = warp_reduce(sse);
    int lane = t & 31, wid = t >> 5;
    if (lane == 0) wsum[wid] = v;
    __syncthreads();
    if (wid == 0) {
        v = (lane < (BX * BY / 32)) ? wsum[lane] : 0.0;
        v = warp_reduce(v);
        if (lane == 0) atomicAdd(&g_acc[flowIdx], v);
    }
}

__global__ void finalize_kernel(float* out, double n0, double n1) {
    double l0 = g_acc[0] / n0 + g_corr[0];
    double l1 = g_acc[1] / n1 + g_corr[1];
    out[0] = (float)(l0 + l1);
}

extern "C" void kernel_launch(void* const* d_in, const int* in_sizes, int n_in,
                              void* d_out, int out_size) {
    const float* f0 = (const float*)d_in[0];
    const float* f1 = (const float*)d_in[1];
    long long s0 = in_sizes[0], s1 = in_sizes[1];
    if (s0 > s1) {  // f0 must be the smaller (W=128, kz=3) flow
        const float* tf = f0; f0 = f1; f1 = tf;
        long long ts = s0; s0 = s1; s1 = ts;
    }
    // shape (32, 2, W, W) -> W = sqrt(size / 64)
    int W0 = (int)llround(sqrt((double)s0 / 64.0));
    int W1 = (int)llround(sqrt((double)s1 / 64.0));
    int o0 = W0 - 3 + 1;
    int o1 = W1 - 5 + 1;

    setup_kernel<3><<<1, 1024>>>(W0, 0);
    setup_kernel<5><<<1, 1024>>>(W1, 1);

    dim3 blk(32, 8);
    dim3 g0((o0 + 31) / 32, (o0 + 7) / 8, 64);
    dim3 g1((o1 + 31) / 32, (o1 + 7) / 8, 64);
    sse_kernel<3><<<g0, blk>>>(f0, W0, o0, 0);
    sse_kernel<5><<<g1, blk>>>(f1, W1, o1, 1);

    finalize_kernel<<<1, 1>>>((float*)d_out, 32.0 * o0 * o0, 32.0 * o1 * o1);
}

// round 2
// speedup vs baseline: 3.6645x; 3.6645x over previous
#include <cuda_runtime.h>
#include <math.h>

// Accumulators live in device globals (no allocation allowed).
__device__ double g_acc[2];

__global__ void zero_kernel() { g_acc[0] = 0.0; g_acc[1] = 0.0; }

__inline__ __device__ double warp_reduce(double v) {
    #pragma unroll
    for (int o = 16; o > 0; o >>= 1) v += __shfl_down_sync(0xffffffffu, v, o);
    return v;
}

// ---------------------------------------------------------------------------
// SSE kernel: per output pixel, affine-fit residual via centered moments.
//   SSE = Q - S^2/n - (Sa^2 + Sc^2)/(KZ*V)
// Register-blocked: each thread computes TY outputs in a column, reusing
// horizontal row statistics through a KZ-deep register shift window.
// ---------------------------------------------------------------------------
template <int KZ, int TY>
__global__ __launch_bounds__(256) void sse_kernel(const float* __restrict__ flow,
                                                  int W, int outN, int slot) {
    constexpr int BX = 32, BY = 8;
    constexpr int ROWS = BY * TY;              // output rows per block
    constexpr int SW = BX + KZ - 1;
    constexpr int SH = ROWS + KZ - 1;
    __shared__ float tile[SH][SW];
    __shared__ double wsum[8];

    const float* src = flow + (size_t)blockIdx.z * W * W;
    int ox0 = blockIdx.x * BX, oy0 = blockIdx.y * ROWS;

    int t = threadIdx.y * BX + threadIdx.x;
    for (int i = t; i < SH * SW; i += BX * BY) {
        int r = i / SW, c = i % SW;
        int gr = oy0 + r, gc = ox0 + c;
        tile[r][c] = (gr < W && gc < W) ? src[gr * W + gc] : 0.0f;
    }
    __syncthreads();

    const float mu = (KZ - 1) * 0.5f;
    float vs = 0.0f;
    #pragma unroll
    for (int i = 0; i < KZ; i++) vs += (i - mu) * (i - mu);
    const float inv_n  = 1.0f / (float)(KZ * KZ);
    const float inv_kv = 1.0f / ((float)KZ * vs);

    const int tx = threadIdx.x;
    const int ry0 = threadIdx.y * TY;          // tile-relative first output row
    const int ox = ox0 + tx;
    const bool xok = (ox < outN);

    float rs[KZ], rc[KZ], rq[KZ];
    float acc = 0.0f;

    #pragma unroll
    for (int r = 0; r < TY + KZ - 1; r++) {
        // horizontal window stats for tile row ry0 + r
        float s = 0.0f, c1 = 0.0f, q = 0.0f;
        #pragma unroll
        for (int c = 0; c < KZ; c++) {
            float p = tile[ry0 + r][tx + c];
            s += p;
            c1 = fmaf((float)c - mu, p, c1);
            q  = fmaf(p, p, q);
        }
        rs[r % KZ] = s; rc[r % KZ] = c1; rq[r % KZ] = q;

        if (r >= KZ - 1) {
            const int r0 = r - (KZ - 1);
            float S = 0.0f, Sc = 0.0f, Q = 0.0f, Sa = 0.0f;
            #pragma unroll
            for (int a = 0; a < KZ; a++) {
                const int j = (r0 + a) % KZ;   // compile-time after unroll
                S  += rs[j];
                Sc += rc[j];
                Q  += rq[j];
                Sa  = fmaf((float)a - mu, rs[j], Sa);
            }
            float sse = Q - S * S * inv_n - (Sa * Sa + Sc * Sc) * inv_kv;
            int oy = oy0 + ry0 + r0;
            if (xok && oy < outN) acc += sse;
        }
    }

    // block reduction -> one atomicAdd per block
    double v = warp_reduce((double)acc);
    int lane = t & 31, wid = t >> 5;
    if (lane == 0) wsum[wid] = v;
    __syncthreads();
    if (wid == 0) {
        v = (lane < 8) ? wsum[lane] : 0.0;
        v = warp_reduce(v);
        if (lane == 0) atomicAdd(&g_acc[slot], v);
    }
}

__global__ void finalize_kernel(float* out, double n0, double n1,
                                double corr0, double corr1) {
    out[0] = (float)(g_acc[0] / n0 + corr0 + g_acc[1] / n1 + corr1);
}

// ---------------------------------------------------------------------------
// Host: replicate the reference's KTK construction (fp64 -> fp32 cast) and
// evaluate the coordinate-bias correction analytically.
// ---------------------------------------------------------------------------
static double host_corr(int kz, int W) {
    const int K2 = kz * kz;
    double st = 0.0, st2 = 0.0;
    for (int i = 0; i < kz; i++) { st += i; st2 += (double)i * i; }
    double G00 = kz * st2, G01 = st * st, G02 = kz * st;
    double G11 = kz * st2, G12 = kz * st, G22 = (double)K2;
    double c00 = G11 * G22 - G12 * G12;
    double c01 = G12 * G02 - G01 * G22;
    double c02 = G01 * G12 - G11 * G02;
    double det = G00 * c00 + G01 * c01 + G02 * c02;
    double id = 1.0 / det;
    double Inv[9] = {
        c00 * id, c01 * id, c02 * id,
        c01 * id, (G00 * G22 - G02 * G02) * id, (G02 * G01 - G00 * G12) * id,
        c02 * id, (G02 * G01 - G00 * G12) * id, (G00 * G11 - G01 * G01) * id
    };

    double Kmat[625];  // K2*K2 <= 625
    for (int q = 0; q < K2; q++) {
        double Aq[3] = { (double)(q / kz), (double)(q % kz), 1.0 };
        for (int r = 0; r < K2; r++) {
            double Ar[3] = { (double)(r / kz), (double)(r % kz), 1.0 };
            double p = 0.0;
            for (int i = 0; i < 3; i++)
                for (int j = 0; j < 3; j++)
                    p += Aq[i] * Inv[i * 3 + j] * Ar[j];
            Kmat[q * K2 + r] = p - (q == r ? 1.0 : 0.0);
        }
    }

    // M32 = float32(K'K), as the reference does
    double alpha = 0.0, betaC = 0.0, gammaC = 0.0, betaA = 0.0, gammaA = 0.0;
    for (int q = 0; q < K2; q++) {
        for (int r = 0; r < K2; r++) {
            double m64 = 0.0;
            for (int s = 0; s < K2; s++) m64 += Kmat[s * K2 + q] * Kmat[s * K2 + r];
            double m = (double)(float)m64;
            double qc = (double)(q % kz), qa = (double)(q / kz);
            double rcv = (double)(r % kz), rav = (double)(r / kz);
            alpha  += m;
            betaC  += m * rcv;
            gammaC += qc * m * rcv;
            betaA  += m * rav;
            gammaA += qa * m * rav;
        }
    }

    double outN = (double)(W - kz + 1);
    double Sw  = outN * (outN - 1.0) * 0.5;
    double Sw2 = (outN - 1.0) * outN * (2.0 * outN - 1.0) / 6.0;
    double corrX = (alpha * Sw2 + 2.0 * betaC * Sw) / outN + gammaC;  // gx
    double corrY = (alpha * Sw2 + 2.0 * betaA * Sw) / outN + gammaA;  // gy
    return corrX + corrY;
}

extern "C" void kernel_launch(void* const* d_in, const int* in_sizes, int n_in,
                              void* d_out, int out_size) {
    const float* f0 = (const float*)d_in[0];
    const float* f1 = (const float*)d_in[1];
    long long s0 = in_sizes[0], s1 = in_sizes[1];
    if (s0 > s1) {  // f0 must be the smaller (kz=3) flow
        const float* tf = f0; f0 = f1; f1 = tf;
        long long ts = s0; s0 = s1; s1 = ts;
    }
    // shape (32, 2, W, W) -> W = sqrt(size / 64)
    int W0 = (int)llround(sqrt((double)s0 / 64.0));
    int W1 = (int)llround(sqrt((double)s1 / 64.0));
    int o0 = W0 - 3 + 1;
    int o1 = W1 - 5 + 1;

    double corr0 = host_corr(3, W0);
    double corr1 = host_corr(5, W1);

    zero_kernel<<<1, 1>>>();

    constexpr int TY = 8;
    dim3 blk(32, 8);
    dim3 g0((o0 + 31) / 32, (o0 + 8 * TY - 1) / (8 * TY), 64);
    dim3 g1((o1 + 31) / 32, (o1 + 8 * TY - 1) / (8 * TY), 64);
    sse_kernel<3, TY><<<g0, blk>>>(f0, W0, o0, 0);
    sse_kernel<5, TY><<<g1, blk>>>(f1, W1, o1, 1);

    finalize_kernel<<<1, 1>>>((float*)d_out, 32.0 * o0 * o0, 32.0 * o1 * o1,
                              corr0, corr1);
}

// round 3
// speedup vs baseline: 4.2005x; 1.1463x over previous
#include <cuda_runtime.h>
#include <math.h>

// Device-global accumulators. Statically initialized; the last block of each
// run reads-and-zeros them (atomicExch) so every graph replay starts clean.
__device__ double g_acc[2] = {0.0, 0.0};
__device__ unsigned int g_done = 0;   // atomicInc auto-wraps to 0 at ntot-1

__inline__ __device__ double warp_reduce(double v) {
    #pragma unroll
    for (int o = 16; o > 0; o >>= 1) v += __shfl_down_sync(0xffffffffu, v, o);
    return v;
}

// ---------------------------------------------------------------------------
// Per-block SSE body: affine-fit residual via centered moments.
//   SSE = Q - S^2/n - (Sa^2 + Sc^2)/(KZ*V)
// Each thread computes TY=8 outputs in a column, reusing horizontal row
// statistics through a KZ-deep register shift window.
// ---------------------------------------------------------------------------
template <int KZ>
__device__ __forceinline__ float body(const float* __restrict__ src, int W,
                                      int outN, int ox0, int oy0,
                                      float* __restrict__ tile) {
    constexpr int TY = 8;
    constexpr int ROWS = 8 * TY;                 // 64 output rows / block
    constexpr int SW = 32 + KZ - 1;
    constexpr int SH = ROWS + KZ - 1;

    const int t = threadIdx.y * 32 + threadIdx.x;
    for (int i = t; i < SH * SW; i += 256) {
        int r = i / SW, c = i % SW;
        int gr = oy0 + r, gc = ox0 + c;
        tile[r * SW + c] = (gr < W && gc < W) ? src[gr * W + gc] : 0.0f;
    }
    __syncthreads();

    const float mu = (KZ - 1) * 0.5f;
    float vs = 0.0f;
    #pragma unroll
    for (int i = 0; i < KZ; i++) vs += (i - mu) * (i - mu);
    const float inv_n  = 1.0f / (float)(KZ * KZ);
    const float inv_kv = 1.0f / ((float)KZ * vs);

    const int tx = threadIdx.x;
    const int ry0 = threadIdx.y * TY;
    const bool xok = (ox0 + tx < outN);

    float rs[KZ], rc[KZ], rq[KZ];
    float acc = 0.0f;

    #pragma unroll
    for (int r = 0; r < TY + KZ - 1; r++) {
        float s = 0.0f, c1 = 0.0f, q = 0.0f;
        #pragma unroll
        for (int c = 0; c < KZ; c++) {
            float p = tile[(ry0 + r) * SW + tx + c];
            s += p;
            c1 = fmaf((float)c - mu, p, c1);
            q  = fmaf(p, p, q);
        }
        rs[r % KZ] = s; rc[r % KZ] = c1; rq[r % KZ] = q;

        if (r >= KZ - 1) {
            const int r0 = r - (KZ - 1);
            float S = 0.0f, Sc = 0.0f, Q = 0.0f, Sa = 0.0f;
            #pragma unroll
            for (int a = 0; a < KZ; a++) {
                const int j = (r0 + a) % KZ;     // compile-time after unroll
                S  += rs[j];
                Sc += rc[j];
                Q  += rq[j];
                Sa  = fmaf((float)a - mu, rs[j], Sa);
            }
            float sse = Q - S * S * inv_n - (Sa * Sa + Sc * Sc) * inv_kv;
            int oy = oy0 + ry0 + r0;
            if (xok && oy < outN) acc += sse;
        }
    }
    return acc;
}

// ---------------------------------------------------------------------------
// Single fused kernel: both flows in one grid + last-block finalize.
// ---------------------------------------------------------------------------
__global__ __launch_bounds__(256) void fused_kernel(
    const float* __restrict__ f0, const float* __restrict__ f1,
    int W0, int o0, int gx0, int gy0,
    int W1, int o1, int gx1, int gy1,
    int nb0, unsigned int ntot,
    double n0, double n1, double corr0, double corr1,
    float* __restrict__ out) {
    __shared__ float tile[68 * 36];       // sized for KZ=5 (SH=68, SW=36)
    __shared__ double wsum[8];

    const int bid = blockIdx.x;
    float acc;
    int slot;
    if (bid < nb0) {
        int bx = bid % gx0;
        int tmp = bid / gx0;
        int by = tmp % gy0;
        int img = tmp / gy0;
        acc = body<3>(f0 + (size_t)img * W0 * W0, W0, o0, bx * 32, by * 64, tile);
        slot = 0;
    } else {
        int lb = bid - nb0;
        int bx = lb % gx1;
        int tmp = lb / gx1;
        int by = tmp % gy1;
        int img = tmp / gy1;
        acc = body<5>(f1 + (size_t)img * W1 * W1, W1, o1, bx * 32, by * 64, tile);
        slot = 1;
    }

    // block reduction
    double v = warp_reduce((double)acc);
    const int t = threadIdx.y * 32 + threadIdx.x;
    const int lane = t & 31, wid = t >> 5;
    if (lane == 0) wsum[wid] = v;
    __syncthreads();
    if (t == 0) {
        double bv = 0.0;
        #pragma unroll
        for (int i = 0; i < 8; i++) bv += wsum[i];
        atomicAdd(&g_acc[slot], bv);
        __threadfence();
        unsigned int old = atomicInc(&g_done, ntot - 1u);  // wraps to 0 at last
        if (old == ntot - 1u) {
            // last block: read-and-zero accumulators, write final loss
            double a0 = __longlong_as_double(
                atomicExch((unsigned long long*)&g_acc[0], 0ull));
            double a1 = __longlong_as_double(
                atomicExch((unsigned long long*)&g_acc[1], 0ull));
            out[0] = (float)(a0 / n0 + corr0 + a1 / n1 + corr1);
        }
    }
}

// ---------------------------------------------------------------------------
// Host: replicate the reference's KTK construction (fp64 -> fp32 cast) and
// evaluate the coordinate-bias correction analytically.
// ---------------------------------------------------------------------------
static double host_corr(int kz, int W) {
    const int K2 = kz * kz;
    double st = 0.0, st2 = 0.0;
    for (int i = 0; i < kz; i++) { st += i; st2 += (double)i * i; }
    double G00 = kz * st2, G01 = st * st, G02 = kz * st;
    double G11 = kz * st2, G12 = kz * st, G22 = (double)K2;
    double c00 = G11 * G22 - G12 * G12;
    double c01 = G12 * G02 - G01 * G22;
    double c02 = G01 * G12 - G11 * G02;
    double det = G00 * c00 + G01 * c01 + G02 * c02;
    double id = 1.0 / det;
    double Inv[9] = {
        c00 * id, c01 * id, c02 * id,
        c01 * id, (G00 * G22 - G02 * G02) * id, (G02 * G01 - G00 * G12) * id,
        c02 * id, (G02 * G01 - G00 * G12) * id, (G00 * G11 - G01 * G01) * id
    };

    double Kmat[625];  // K2*K2 <= 625
    for (int q = 0; q < K2; q++) {
        double Aq[3] = { (double)(q / kz), (double)(q % kz), 1.0 };
        for (int r = 0; r < K2; r++) {
            double Ar[3] = { (double)(r / kz), (double)(r % kz), 1.0 };
            double p = 0.0;
            for (int i = 0; i < 3; i++)
                for (int j = 0; j < 3; j++)
                    p += Aq[i] * Inv[i * 3 + j] * Ar[j];
            Kmat[q * K2 + r] = p - (q == r ? 1.0 : 0.0);
        }
    }

    double alpha = 0.0, betaC = 0.0, gammaC = 0.0, betaA = 0.0, gammaA = 0.0;
    for (int q = 0; q < K2; q++) {
        for (int r = 0; r < K2; r++) {
            double m64 = 0.0;
            for (int s = 0; s < K2; s++) m64 += Kmat[s * K2 + q] * Kmat[s * K2 + r];
            double m = (double)(float)m64;   // fp32 cast exactly like reference
            double qc = (double)(q % kz), qa = (double)(q / kz);
            double rcv = (double)(r % kz), rav = (double)(r / kz);
            alpha  += m;
            betaC  += m * rcv;
            gammaC += qc * m * rcv;
            betaA  += m * rav;
            gammaA += qa * m * rav;
        }
    }

    double outN = (double)(W - kz + 1);
    double Sw  = outN * (outN - 1.0) * 0.5;
    double Sw2 = (outN - 1.0) * outN * (2.0 * outN - 1.0) / 6.0;
    double corrX = (alpha * Sw2 + 2.0 * betaC * Sw) / outN + gammaC;  // gx
    double corrY = (alpha * Sw2 + 2.0 * betaA * Sw) / outN + gammaA;  // gy
    return corrX + corrY;
}

extern "C" void kernel_launch(void* const* d_in, const int* in_sizes, int n_in,
                              void* d_out, int out_size) {
    const float* f0 = (const float*)d_in[0];
    const float* f1 = (const float*)d_in[1];
    long long s0 = in_sizes[0], s1 = in_sizes[1];
    if (s0 > s1) {  // f0 must be the smaller (kz=3) flow
        const float* tf = f0; f0 = f1; f1 = tf;
        long long ts = s0; s0 = s1; s1 = ts;
    }
    // shape (32, 2, W, W) -> W = sqrt(size / 64)
    int W0 = (int)llround(sqrt((double)s0 / 64.0));
    int W1 = (int)llround(sqrt((double)s1 / 64.0));
    int o0 = W0 - 3 + 1;
    int o1 = W1 - 5 + 1;

    double corr0 = host_corr(3, W0);
    double corr1 = host_corr(5, W1);

    int gx0 = (o0 + 31) / 32, gy0 = (o0 + 63) / 64;
    int gx1 = (o1 + 31) / 32, gy1 = (o1 + 63) / 64;
    int nb0 = gx0 * gy0 * 64;
    int nb1 = gx1 * gy1 * 64;
    unsigned int ntot = (unsigned int)(nb0 + nb1);

    dim3 blk(32, 8);
    fused_kernel<<<ntot, blk>>>(f0, f1,
                                W0, o0, gx0, gy0,
                                W1, o1, gx1, gy1,
                                nb0, ntot,
                                32.0 * o0 * o0, 32.0 * o1 * o1,
                                corr0, corr1,
                                (float*)d_out);
}

// round 4
// speedup vs baseline: 4.5755x; 1.0893x over previous
#include <cuda_runtime.h>
#include <math.h>

// Device-global accumulators. Last block reads-and-zeros them (atomicExch) so
// every graph replay starts clean. g_done auto-wraps via atomicInc.
__device__ double g_acc[2] = {0.0, 0.0};
__device__ unsigned int g_done = 0;

__inline__ __device__ double warp_reduce(double v) {
    #pragma unroll
    for (int o = 16; o > 0; o >>= 1) v += __shfl_down_sync(0xffffffffu, v, o);
    return v;
}

// ---------------------------------------------------------------------------
// Per-block SSE body: affine-fit residual via centered moments.
//   SSE = Q - S^2/n - (Sa^2 + Sc^2)/(KZ*V)
// Each thread computes TX=2 adjacent output columns x TY=8 output rows.
// Horizontal stats: col0 full, col1 by window-shift identity.
// Vertical: incremental sliding of the 4 moments through a KZ-deep register
// history.
// ---------------------------------------------------------------------------
template <int KZ>
__device__ __forceinline__ float body(const float* __restrict__ src, int W,
                                      int outN, int ox0, int oy0,
                                      float* __restrict__ tile) {
    constexpr int TY = 8;
    constexpr int ROWS = 8 * TY;          // 64 output rows per block
    constexpr int COLS = 64;              // 64 output cols per block
    constexpr int SW = COLS + KZ - 1;     // even (KZ odd)
    constexpr int SH = ROWS + KZ - 1;
    constexpr int SW2 = SW / 2;
    constexpr int NV = KZ + 2;            // window values per thread per row
    constexpr int NL = (NV + 1) / 2;      // float2 loads per row

    const int t = threadIdx.y * 32 + threadIdx.x;

    // float2-vectorized tile fill (zero-padded at borders)
    for (int i = t; i < SH * SW2; i += 256) {
        int r = i / SW2, c2 = (i - r * SW2) * 2;
        int gr = oy0 + r, gc = ox0 + c2;
        float2 v = make_float2(0.0f, 0.0f);
        if (gr < W) {
            if (gc + 1 < W)
                v = *reinterpret_cast<const float2*>(&src[gr * W + gc]);
            else if (gc < W)
                v.x = src[gr * W + gc];
        }
        *reinterpret_cast<float2*>(&tile[r * SW + c2]) = v;
    }
    __syncthreads();

    const float mu = (KZ - 1) * 0.5f;
    float vsum = 0.0f;
    #pragma unroll
    for (int i = 0; i < KZ; i++) vsum += (i - mu) * (i - mu);
    const float inv_n  = 1.0f / (float)(KZ * KZ);
    const float inv_kv = 1.0f / ((float)KZ * vsum);
    const float whi = (float)KZ - mu;

    const int c0 = 2 * threadIdx.x;
    const int ry0 = threadIdx.y * TY;
    const bool ok0 = (ox0 + c0     < outN);
    const bool ok1 = (ox0 + c0 + 1 < outN);

    float hs[KZ][2], hc[KZ][2], hq[KZ][2];
    float S[2], Sc[2], Q[2], Sa[2];
    float acc = 0.0f;

    #pragma unroll
    for (int r = 0; r < TY + KZ - 1; r++) {
        // load the NV-value window for this row (aligned float2 LDS)
        float p[NL * 2];
        #pragma unroll
        for (int j = 0; j < NL; j++) {
            float2 v = *reinterpret_cast<const float2*>(
                &tile[(ry0 + r) * SW + c0 + 2 * j]);
            p[2 * j] = v.x; p[2 * j + 1] = v.y;
        }
        // column-0 row stats
        float s0 = 0.0f, cc0 = 0.0f, q0 = 0.0f;
        #pragma unroll
        for (int c = 0; c < KZ; c++) {
            s0 += p[c];
            cc0 = fmaf((float)c - mu, p[c], cc0);
            q0  = fmaf(p[c], p[c], q0);
        }
        // column-1 row stats via horizontal shift identity
        float s1  = s0 - p[0] + p[KZ];
        float cc1 = cc0 + mu * p[0] + whi * p[KZ] - s1;
        float q1  = fmaf(p[KZ], p[KZ], q0 - p[0] * p[0]);

        const int slot = r % KZ;             // constant after unroll
        if (r >= KZ) {
            // vertical incremental update (use old slot values before overwrite)
            float os0 = hs[slot][0], os1 = hs[slot][1];
            S[0]  += s0 - os0;               S[1]  += s1 - os1;
            Sc[0] += cc0 - hc[slot][0];      Sc[1] += cc1 - hc[slot][1];
            Q[0]  += q0 - hq[slot][0];       Q[1]  += q1 - hq[slot][1];
            Sa[0]  = Sa[0] + mu * os0 + whi * s0 - S[0];
            Sa[1]  = Sa[1] + mu * os1 + whi * s1 - S[1];
        }
        hs[slot][0] = s0;  hs[slot][1] = s1;
        hc[slot][0] = cc0; hc[slot][1] = cc1;
        hq[slot][0] = q0;  hq[slot][1] = q1;

        if (r == KZ - 1) {
            // first full window: direct combine
            #pragma unroll
            for (int j = 0; j < 2; j++) { S[j] = 0; Sc[j] = 0; Q[j] = 0; Sa[j] = 0; }
            #pragma unroll
            for (int a = 0; a < KZ; a++)
                #pragma unroll
                for (int j = 0; j < 2; j++) {
                    S[j]  += hs[a][j];
                    Sc[j] += hc[a][j];
                    Q[j]  += hq[a][j];
                    Sa[j]  = fmaf((float)a - mu, hs[a][j], Sa[j]);
                }
        }
        if (r >= KZ - 1) {
            int oy = oy0 + ry0 + r - (KZ - 1);
            if (oy < outN) {
                float e0 = Q[0] - S[0]*S[0]*inv_n - (Sa[0]*Sa[0] + Sc[0]*Sc[0])*inv_kv;
                float e1 = Q[1] - S[1]*S[1]*inv_n - (Sa[1]*Sa[1] + Sc[1]*Sc[1])*inv_kv;
                if (ok0) acc += e0;
                if (ok1) acc += e1;
            }
        }
    }
    return acc;
}

// ---------------------------------------------------------------------------
// Single fused kernel: both flows in one grid + last-block finalize.
// kz=5 blocks scheduled first (longest work starts earliest).
// ---------------------------------------------------------------------------
__global__ __launch_bounds__(256) void fused_kernel(
    const float* __restrict__ f0, const float* __restrict__ f1,
    int W0, int o0, int gx0, int gy0,
    int W1, int o1, int gx1, int gy1,
    int nb1, unsigned int ntot,
    double n0, double n1, double corr0, double corr1,
    float* __restrict__ out) {
    __shared__ float tile[68 * 68];       // sized for KZ=5 (SH=SW=68)
    __shared__ double wsum[8];

    const int bid = blockIdx.x;
    float acc;
    int slot;
    if (bid < nb1) {                      // kz=5 flow first
        int bx = bid % gx1;
        int tmp = bid / gx1;
        int by = tmp % gy1;
        int img = tmp / gy1;
        acc = body<5>(f1 + (size_t)img * W1 * W1, W1, o1, bx * 64, by * 64, tile);
        slot = 1;
    } else {
        int lb = bid - nb1;
        int bx = lb % gx0;
        int tmp = lb / gx0;
        int by = tmp % gy0;
        int img = tmp / gy0;
        acc = body<3>(f0 + (size_t)img * W0 * W0, W0, o0, bx * 64, by * 64, tile);
        slot = 0;
    }

    // block reduction -> one atomicAdd per block
    double v = warp_reduce((double)acc);
    const int t = threadIdx.y * 32 + threadIdx.x;
    const int lane = t & 31, wid = t >> 5;
    if (lane == 0) wsum[wid] = v;
    __syncthreads();
    if (t == 0) {
        double bv = 0.0;
        #pragma unroll
        for (int i = 0; i < 8; i++) bv += wsum[i];
        atomicAdd(&g_acc[slot], bv);
        __threadfence();
        unsigned int old = atomicInc(&g_done, ntot - 1u);  // wraps to 0 at last
        if (old == ntot - 1u) {
            double a0 = __longlong_as_double(
                atomicExch((unsigned long long*)&g_acc[0], 0ull));
            double a1 = __longlong_as_double(
                atomicExch((unsigned long long*)&g_acc[1], 0ull));
            out[0] = (float)(a0 / n0 + corr0 + a1 / n1 + corr1);
        }
    }
}

// ---------------------------------------------------------------------------
// Host: replicate the reference's KTK construction (fp64 -> fp32 cast) and
// evaluate the coordinate-bias correction analytically.
// ---------------------------------------------------------------------------
static double host_corr(int kz, int W) {
    const int K2 = kz * kz;
    double st = 0.0, st2 = 0.0;
    for (int i = 0; i < kz; i++) { st += i; st2 += (double)i * i; }
    double G00 = kz * st2, G01 = st * st, G02 = kz * st;
    double G11 = kz * st2, G12 = kz * st, G22 = (double)K2;
    double c00 = G11 * G22 - G12 * G12;
    double c01 = G12 * G02 - G01 * G22;
    double c02 = G01 * G12 - G11 * G02;
    double det = G00 * c00 + G01 * c01 + G02 * c02;
    double id = 1.0 / det;
    double Inv[9] = {
        c00 * id, c01 * id, c02 * id,
        c01 * id, (G00 * G22 - G02 * G02) * id, (G02 * G01 - G00 * G12) * id,
        c02 * id, (G02 * G01 - G00 * G12) * id, (G00 * G11 - G01 * G01) * id
    };

    double Kmat[625];  // K2*K2 <= 625
    for (int q = 0; q < K2; q++) {
        double Aq[3] = { (double)(q / kz), (double)(q % kz), 1.0 };
        for (int r = 0; r < K2; r++) {
            double Ar[3] = { (double)(r / kz), (double)(r % kz), 1.0 };
            double p = 0.0;
            for (int i = 0; i < 3; i++)
                for (int j = 0; j < 3; j++)
                    p += Aq[i] * Inv[i * 3 + j] * Ar[j];
            Kmat[q * K2 + r] = p - (q == r ? 1.0 : 0.0);
        }
    }

    double alpha = 0.0, betaC = 0.0, gammaC = 0.0, betaA = 0.0, gammaA = 0.0;
    for (int q = 0; q < K2; q++) {
        for (int r = 0; r < K2; r++) {
            double m64 = 0.0;
            for (int s = 0; s < K2; s++) m64 += Kmat[s * K2 + q] * Kmat[s * K2 + r];
            double m = (double)(float)m64;   // fp32 cast exactly like reference
            double qc = (double)(q % kz), qa = (double)(q / kz);
            double rcv = (double)(r % kz), rav = (double)(r / kz);
            alpha  += m;
            betaC  += m * rcv;
            gammaC += qc * m * rcv;
            betaA  += m * rav;
            gammaA += qa * m * rav;
        }
    }

    double outN = (double)(W - kz + 1);
    double Sw  = outN * (outN - 1.0) * 0.5;
    double Sw2 = (outN - 1.0) * outN * (2.0 * outN - 1.0) / 6.0;
    double corrX = (alpha * Sw2 + 2.0 * betaC * Sw) / outN + gammaC;  // gx
    double corrY = (alpha * Sw2 + 2.0 * betaA * Sw) / outN + gammaA;  // gy
    return corrX + corrY;
}

extern "C" void kernel_launch(void* const* d_in, const int* in_sizes, int n_in,
                              void* d_out, int out_size) {
    const float* f0 = (const float*)d_in[0];
    const float* f1 = (const float*)d_in[1];
    long long s0 = in_sizes[0], s1 = in_sizes[1];
    if (s0 > s1) {  // f0 must be the smaller (kz=3) flow
        const float* tf = f0; f0 = f1; f1 = tf;
        long long ts = s0; s0 = s1; s1 = ts;
    }
    // shape (32, 2, W, W) -> W = sqrt(size / 64)
    int W0 = (int)llround(sqrt((double)s0 / 64.0));
    int W1 = (int)llround(sqrt((double)s1 / 64.0));
    int o0 = W0 - 3 + 1;
    int o1 = W1 - 5 + 1;

    double corr0 = host_corr(3, W0);
    double corr1 = host_corr(5, W1);

    int gx0 = (o0 + 63) / 64, gy0 = (o0 + 63) / 64;
    int gx1 = (o1 + 63) / 64, gy1 = (o1 + 63) / 64;
    int nb0 = gx0 * gy0 * 64;
    int nb1 = gx1 * gy1 * 64;
    unsigned int ntot = (unsigned int)(nb0 + nb1);

    dim3 blk(32, 8);
    fused_kernel<<<ntot, blk>>>(f0, f1,
                                W0, o0, gx0, gy0,
                                W1, o1, gx1, gy1,
                                nb1, ntot,
                                32.0 * o0 * o0, 32.0 * o1 * o1,
                                corr0, corr1,
                                (float*)d_out);
}

// round 5
// speedup vs baseline: 5.5517x; 1.2133x over previous
#include <cuda_runtime.h>
#include <math.h>

typedef unsigned long long u64;

// Device-global accumulators. Last block reads-and-zeros them (atomicExch) so
// every graph replay starts clean. g_done auto-wraps via atomicInc.
__device__ double g_acc[2] = {0.0, 0.0};
__device__ unsigned int g_done = 0;

// ---- packed f32x2 helpers (Blackwell FFMA2 path) ---------------------------
__device__ __forceinline__ u64 pack2(float lo, float hi) {
    u64 r; asm("mov.b64 %0, {%1, %2};" : "=l"(r) : "f"(lo), "f"(hi)); return r;
}
__device__ __forceinline__ void punpack(u64 a, float& x, float& y) {
    asm("mov.b64 {%0, %1}, %2;" : "=f"(x), "=f"(y) : "l"(a));
}
__device__ __forceinline__ u64 padd(u64 a, u64 b) {
    u64 r; asm("add.rn.f32x2 %0, %1, %2;" : "=l"(r) : "l"(a), "l"(b)); return r;
}
__device__ __forceinline__ u64 pmul(u64 a, u64 b) {
    u64 r; asm("mul.rn.f32x2 %0, %1, %2;" : "=l"(r) : "l"(a), "l"(b)); return r;
}
__device__ __forceinline__ u64 pfma(u64 a, u64 b, u64 c) {
    u64 r; asm("fma.rn.f32x2 %0, %1, %2, %3;" : "=l"(r) : "l"(a), "l"(b), "l"(c));
    return r;
}

__inline__ __device__ double warp_reduce(double v) {
    #pragma unroll
    for (int o = 16; o > 0; o >>= 1) v += __shfl_down_sync(0xffffffffu, v, o);
    return v;
}

// ---------------------------------------------------------------------------
// Per-block SSE body: affine-fit residual via centered moments.
//   SSE = Q - S^2/n - (Sa^2 + Sc^2)/(KZ*V)
// Each thread computes 2 adjacent output columns x 8 output rows, with ALL
// moment math done in packed f32x2 (both columns per instruction).
// ---------------------------------------------------------------------------
template <int KZ>
__device__ __forceinline__ float body(const float* __restrict__ src, int W,
                                      int outN, int ox0, int oy0,
                                      float* __restrict__ tile) {
    constexpr int TY = 8;
    constexpr int SW = 68;                  // padded width (fits kz3 & kz5)
    constexpr int SH = 64 + KZ - 1;
    constexpr int NV = KZ + 2;              // window values per thread per row
    constexpr int NL = (NV + 1) / 2;        // float2 loads per row

    const int t = threadIdx.y * 32 + threadIdx.x;

    // float4-vectorized tile fill (zero-padded at borders). SW=68=4*17.
    for (int i = t; i < SH * 17; i += 256) {
        int r = i / 17, c4 = (i - r * 17) * 4;
        int gr = oy0 + r, gc = ox0 + c4;
        float4 v = make_float4(0.f, 0.f, 0.f, 0.f);
        if (gr < W) {
            if (gc + 3 < W) {
                v = *reinterpret_cast<const float4*>(&src[gr * W + gc]);
            } else {
                const float* row = &src[gr * W];
                if (gc     < W) v.x = row[gc];
                if (gc + 1 < W) v.y = row[gc + 1];
                if (gc + 2 < W) v.z = row[gc + 2];
                if (gc + 3 < W) v.w = row[gc + 3];
            }
        }
        *reinterpret_cast<float4*>(&tile[r * SW + c4]) = v;
    }
    __syncthreads();

    const float mu = (KZ - 1) * 0.5f;
    float vsum = 0.0f;
    #pragma unroll
    for (int i = 0; i < KZ; i++) vsum += (i - mu) * (i - mu);
    const float inv_n  = 1.0f / (float)(KZ * KZ);
    const float inv_kv = 1.0f / ((float)KZ * vsum);
    const float whi = (float)KZ - mu;

    const u64 NEG1   = pack2(-1.0f, -1.0f);
    const u64 MUp    = pack2(mu, mu);
    const u64 WHIp   = pack2(whi, whi);
    const u64 NINVN  = pack2(-inv_n, -inv_n);
    const u64 NINVKV = pack2(-inv_kv, -inv_kv);

    const int c0 = 2 * threadIdx.x;
    const int ry0 = threadIdx.y * TY;
    const u64 maskP = pack2((ox0 + c0 < outN) ? 1.0f : 0.0f,
                            (ox0 + c0 + 1 < outN) ? 1.0f : 0.0f);

    u64 hs[KZ], hc[KZ], hq[KZ];
    u64 S, Sc, Q, Sa;
    u64 accP = pack2(0.0f, 0.0f);

    #pragma unroll
    for (int r = 0; r < TY + KZ - 1; r++) {
        // load window values p[0..NV-1] via aligned LDS.64
        float p[NL * 2];
        #pragma unroll
        for (int j = 0; j < NL; j++) {
            float2 v = *reinterpret_cast<const float2*>(
                &tile[(ry0 + r) * SW + c0 + 2 * j]);
            p[2 * j] = v.x; p[2 * j + 1] = v.y;
        }
        // shifted column pairs P[c] = {p[c], p[c+1]}
        u64 P[KZ];
        #pragma unroll
        for (int c = 0; c < KZ; c++) P[c] = pack2(p[c], p[c + 1]);

        // row stats for BOTH columns per packed op
        u64 s = P[0];
        #pragma unroll
        for (int c = 1; c < KZ; c++) s = padd(s, P[c]);

        u64 cc;
        if (KZ == 3) {
            cc = pfma(P[0], NEG1, P[2]);                 // P2 - P0
        } else {                                          // KZ == 5
            u64 d1 = pfma(P[1], NEG1, P[3]);             // P3 - P1
            u64 d2 = pfma(P[0], NEG1, P[4]);             // P4 - P0
            cc = padd(d1, padd(d2, d2));                 // d1 + 2*d2
        }

        u64 q = pmul(P[0], P[0]);
        #pragma unroll
        for (int c = 1; c < KZ; c++) q = pfma(P[c], P[c], q);

        const int slot = r % KZ;                          // compile-time
        if (r >= KZ) {
            u64 os = hs[slot];
            S  = padd(S,  pfma(os,       NEG1, s));
            Sc = padd(Sc, pfma(hc[slot], NEG1, cc));
            Q  = padd(Q,  pfma(hq[slot], NEG1, q));
            Sa = pfma(os, MUp, Sa);
            Sa = pfma(s,  WHIp, Sa);
            Sa = pfma(S,  NEG1, Sa);
        }
        hs[slot] = s; hc[slot] = cc; hq[slot] = q;

        if (r == KZ - 1) {                                // first full window
            S = hs[0]; Sc = hc[0]; Q = hq[0];
            #pragma unroll
            for (int a = 1; a < KZ; a++) {
                S  = padd(S,  hs[a]);
                Sc = padd(Sc, hc[a]);
                Q  = padd(Q,  hq[a]);
            }
            Sa = pmul(hs[0], pack2(0.0f - mu, 0.0f - mu));
            #pragma unroll
            for (int a = 1; a < KZ; a++) {
                if ((float)a != mu)
                    Sa = pfma(hs[a], pack2((float)a - mu, (float)a - mu), Sa);
            }
        }
        if (r >= KZ - 1) {
            int oy = oy0 + ry0 + r - (KZ - 1);
            if (oy < outN) {
                u64 u = pmul(S, S);
                u64 v = pmul(Sa, Sa);
                v = pfma(Sc, Sc, v);
                u64 e = pfma(u, NINVN, Q);
                e = pfma(v, NINVKV, e);
                accP = pfma(e, maskP, accP);
            }
        }
    }

    float a0, a1;
    punpack(accP, a0, a1);
    return a0 + a1;
}

// ---------------------------------------------------------------------------
// Single fused kernel: both flows in one grid + last-block finalize.
// kz=5 blocks scheduled first (heaviest work starts earliest).
// ---------------------------------------------------------------------------
__global__ __launch_bounds__(256) void fused_kernel(
    const float* __restrict__ f0, const float* __restrict__ f1,
    int W0, int o0, int gx0, int gy0,
    int W1, int o1, int gx1, int gy1,
    int nb1, unsigned int ntot,
    double n0, double n1, double corr0, double corr1,
    float* __restrict__ out) {
    __shared__ __align__(16) float tile[68 * 68];
    __shared__ double wsum[8];

    const int bid = blockIdx.x;
    float acc;
    int slot;
    if (bid < nb1) {                      // kz=5 flow first
        int bx = bid % gx1;
        int tmp = bid / gx1;
        int by = tmp % gy1;
        int img = tmp / gy1;
        acc = body<5>(f1 + (size_t)img * W1 * W1, W1, o1, bx * 64, by * 64, tile);
        slot = 1;
    } else {
        int lb = bid - nb1;
        int bx = lb % gx0;
        int tmp = lb / gx0;
        int by = tmp % gy0;
        int img = tmp / gy0;
        acc = body<3>(f0 + (size_t)img * W0 * W0, W0, o0, bx * 64, by * 64, tile);
        slot = 0;
    }

    // block reduction -> one atomicAdd per block
    double v = warp_reduce((double)acc);
    const int t = threadIdx.y * 32 + threadIdx.x;
    const int lane = t & 31, wid = t >> 5;
    if (lane == 0) wsum[wid] = v;
    __syncthreads();
    if (t == 0) {
        double bv = 0.0;
        #pragma unroll
        for (int i = 0; i < 8; i++) bv += wsum[i];
        atomicAdd(&g_acc[slot], bv);
        __threadfence();
        unsigned int old = atomicInc(&g_done, ntot - 1u);  // wraps to 0 at last
        if (old == ntot - 1u) {
            double a0 = __longlong_as_double(
                atomicExch((unsigned long long*)&g_acc[0], 0ull));
            double a1 = __longlong_as_double(
                atomicExch((unsigned long long*)&g_acc[1], 0ull));
            out[0] = (float)(a0 / n0 + corr0 + a1 / n1 + corr1);
        }
    }
}

// ---------------------------------------------------------------------------
// Host: replicate the reference's KTK construction (fp64 -> fp32 cast) and
// evaluate the coordinate-bias correction analytically.
// ---------------------------------------------------------------------------
static double host_corr(int kz, int W) {
    const int K2 = kz * kz;
    double st = 0.0, st2 = 0.0;
    for (int i = 0; i < kz; i++) { st += i; st2 += (double)i * i; }
    double G00 = kz * st2, G01 = st * st, G02 = kz * st;
    double G11 = kz * st2, G12 = kz * st, G22 = (double)K2;
    double c00 = G11 * G22 - G12 * G12;
    double c01 = G12 * G02 - G01 * G22;
    double c02 = G01 * G12 - G11 * G02;
    double det = G00 * c00 + G01 * c01 + G02 * c02;
    double id = 1.0 / det;
    double Inv[9] = {
        c00 * id, c01 * id, c02 * id,
        c01 * id, (G00 * G22 - G02 * G02) * id, (G02 * G01 - G00 * G12) * id,
        c02 * id, (G02 * G01 - G00 * G12) * id, (G00 * G11 - G01 * G01) * id
    };

    double Kmat[625];  // K2*K2 <= 625
    for (int q = 0; q < K2; q++) {
        double Aq[3] = { (double)(q / kz), (double)(q % kz), 1.0 };
        for (int r = 0; r < K2; r++) {
            double Ar[3] = { (double)(r / kz), (double)(r % kz), 1.0 };
            double p = 0.0;
            for (int i = 0; i < 3; i++)
                for (int j = 0; j < 3; j++)
                    p += Aq[i] * Inv[i * 3 + j] * Ar[j];
            Kmat[q * K2 + r] = p - (q == r ? 1.0 : 0.0);
        }
    }

    double alpha = 0.0, betaC = 0.0, gammaC = 0.0, betaA = 0.0, gammaA = 0.0;
    for (int q = 0; q < K2; q++) {
        for (int r = 0; r < K2; r++) {
            double m64 = 0.0;
            for (int s = 0; s < K2; s++) m64 += Kmat[s * K2 + q] * Kmat[s * K2 + r];
            double m = (double)(float)m64;   // fp32 cast exactly like reference
            double qc = (double)(q % kz), qa = (double)(q / kz);
            double rcv = (double)(r % kz), rav = (double)(r / kz);
            alpha  += m;
            betaC  += m * rcv;
            gammaC += qc * m * rcv;
            betaA  += m * rav;
            gammaA += qa * m * rav;
        }
    }

    double outN = (double)(W - kz + 1);
    double Sw  = outN * (outN - 1.0) * 0.5;
    double Sw2 = (outN - 1.0) * outN * (2.0 * outN - 1.0) / 6.0;
    double corrX = (alpha * Sw2 + 2.0 * betaC * Sw) / outN + gammaC;  // gx
    double corrY = (alpha * Sw2 + 2.0 * betaA * Sw) / outN + gammaA;  // gy
    return corrX + corrY;
}

extern "C" void kernel_launch(void* const* d_in, const int* in_sizes, int n_in,
                              void* d_out, int out_size) {
    const float* f0 = (const float*)d_in[0];
    const float* f1 = (const float*)d_in[1];
    long long s0 = in_sizes[0], s1 = in_sizes[1];
    if (s0 > s1) {  // f0 must be the smaller (kz=3) flow
        const float* tf = f0; f0 = f1; f1 = tf;
        long long ts = s0; s0 = s1; s1 = ts;
    }
    // shape (32, 2, W, W) -> W = sqrt(size / 64)
    int W0 = (int)llround(sqrt((double)s0 / 64.0));
    int W1 = (int)llround(sqrt((double)s1 / 64.0));
    int o0 = W0 - 3 + 1;
    int o1 = W1 - 5 + 1;

    double corr0 = host_corr(3, W0);
    double corr1 = host_corr(5, W1);

    int gx0 = (o0 + 63) / 64, gy0 = (o0 + 63) / 64;
    int gx1 = (o1 + 63) / 64, gy1 = (o1 + 63) / 64;
    int nb0 = gx0 * gy0 * 64;
    int nb1 = gx1 * gy1 * 64;
    unsigned int ntot = (unsigned int)(nb0 + nb1);

    dim3 blk(32, 8);
    fused_kernel<<<ntot, blk>>>(f0, f1,
                                W0, o0, gx0, gy0,
                                W1, o1, gx1, gy1,
                                nb1, ntot,
                                32.0 * o0 * o0, 32.0 * o1 * o1,
                                corr0, corr1,
                                (float*)d_out);
}